// round 8
// baseline (speedup 1.0000x reference)
#include <cuda_runtime.h>
#include <cstdint>
#include <math.h>

#define T_TOK 2048
#define NE 8
#define DDIM 768
#define HDIM 3072
#define NSLOT (T_TOK * 2)
#define K4X (DDIM / 4)   // 192
#define K4H (HDIM / 4)   // 768

#define BM 128
#define BN 128
#define BK 16

// ---------------------------------------------------------------- scratch
__device__ int   g_ok;
__device__ int   g_max[5];        // |max| as float bits: x, w1, w2, wp, act
__device__ float g_scl[8];        // 0..4 inv-scales (x,w1,w2,wp,act); 5,6,7 products
__device__ float g_h[(size_t)NSLOT * HDIM];   // h, then act fp32
__device__ float g_g[(size_t)NSLOT * HDIM];
__device__ float g_y[(size_t)NSLOT * DDIM];
// packed int8 hi/lo (4 k per u32)
__device__ uint32_t g_xqh[T_TOK * K4X];
__device__ uint32_t g_xql[T_TOK * K4X];
__device__ uint32_t g_w1qh[(size_t)NE * HDIM * K4X];   // [e][h][d4]
__device__ uint32_t g_w1ql[(size_t)NE * HDIM * K4X];
__device__ uint32_t g_w2qh[(size_t)NE * HDIM * K4X];
__device__ uint32_t g_w2ql[(size_t)NE * HDIM * K4X];
__device__ uint32_t g_wpqh[(size_t)NE * DDIM * K4H];   // [e][d][h4]
__device__ uint32_t g_wpql[(size_t)NE * DDIM * K4H];
__device__ uint32_t g_aqh[(size_t)NSLOT * K4H];
__device__ uint32_t g_aql[(size_t)NSLOT * K4H];
// routing
__device__ int   g_cnt[NE];
__device__ int   g_cnt2[NE];
__device__ int   g_off[NE];
__device__ float g_probs[NE];
__device__ int   g_slot_token[NSLOT];
__device__ int   g_tok_slot[NSLOT];
__device__ float g_tok_gate[NSLOT];
__device__ int   g_tok_exp[NSLOT];

__device__ __forceinline__ int flag_on() { return *(volatile int*)&g_ok; }

// ---------------------------------------------------------------- init
__global__ void zero_stats() {
    int i = threadIdx.x;
    if (i < NE) { g_cnt[i] = 0; g_probs[i] = 0.f; }
    if (i < 5)  g_max[i] = 0;
    if (i == 0) g_ok = 1;
}

// ---------------------------------------------------------------- gate path
__global__ void gate_kernel(const float* __restrict__ x,
                            const float* __restrict__ noise,
                            const float* __restrict__ gw,
                            const float* __restrict__ nw,
                            float* __restrict__ out_ids)
{
    int t = blockIdx.x;
    int tid = threadIdx.x;
    const float* xr = x + (size_t)t * DDIM;

    float acc[NE];
#pragma unroll
    for (int e = 0; e < NE; e++) acc[e] = 0.f;
    for (int d = tid; d < DDIM; d += 128) {
        float xv = xr[d];
        const float* w = gw + d * NE;
#pragma unroll
        for (int e = 0; e < NE; e++) acc[e] += xv * w[e];
    }

    __shared__ float sm[NE][128];
#pragma unroll
    for (int e = 0; e < NE; e++) sm[e][tid] = acc[e];
    __syncthreads();
    for (int s = 64; s > 0; s >>= 1) {
        if (tid < s) {
#pragma unroll
            for (int e = 0; e < NE; e++) sm[e][tid] += sm[e][tid + s];
        }
        __syncthreads();
    }

    if (tid == 0) {
        float lg[NE], ns[NE];
#pragma unroll
        for (int e = 0; e < NE; e++) {
            lg[e] = sm[e][0];
            ns[e] = lg[e] + noise[t * NE + e] * nw[e];
        }
        int i0 = 0;
#pragma unroll
        for (int e = 1; e < NE; e++) if (ns[e] > ns[i0]) i0 = e;
        int i1 = (i0 == 0) ? 1 : 0;
#pragma unroll
        for (int e = 0; e < NE; e++) if (e != i0 && ns[e] > ns[i1]) i1 = e;

        float q  = expf(ns[i1] - ns[i0]);
        float p1 = q / (1.f + q);
        float p0 = 1.f - p1;

        g_tok_exp[t * 2 + 0] = i0;  g_tok_exp[t * 2 + 1] = i1;
        g_tok_gate[t * 2 + 0] = p0; g_tok_gate[t * 2 + 1] = p1;
        if (out_ids) {
            out_ids[t * 2 + 0] = (float)i0;
            out_ids[t * 2 + 1] = (float)i1;
        }
        atomicAdd(&g_cnt[i0], 1);
        atomicAdd(&g_cnt[i1], 1);

        float m = lg[0];
#pragma unroll
        for (int e = 1; e < NE; e++) m = fmaxf(m, lg[e]);
        float ex[NE], sum = 0.f;
#pragma unroll
        for (int e = 0; e < NE; e++) { ex[e] = expf(lg[e] - m); sum += ex[e]; }
        float inv = 1.f / sum;
#pragma unroll
        for (int e = 0; e < NE; e++) atomicAdd(&g_probs[e], ex[e] * inv);
    }
}

__global__ void finalize_kernel(float* __restrict__ out_lb) {
    if (threadIdx.x == 0 && blockIdx.x == 0) {
        int off = 0;
        for (int e = 0; e < NE; e++) { g_off[e] = off; off += g_cnt[e]; g_cnt2[e] = 0; }
        float accv = 0.f;
        for (int e = 0; e < NE; e++) {
            float d = g_probs[e] / (float)T_TOK - 1.0f / (float)NE;
            accv += d * d;
        }
        if (out_lb) out_lb[0] = accv / (float)NE * 0.01f;
    }
}

__global__ void scatter_kernel() {
    int t = blockIdx.x * blockDim.x + threadIdx.x;
    if (t >= T_TOK) return;
#pragma unroll
    for (int k2 = 0; k2 < 2; k2++) {
        int e = g_tok_exp[t * 2 + k2];
        int pos = atomicAdd(&g_cnt2[e], 1);
        int slot = g_off[e] + pos;
        g_slot_token[slot] = t;
        g_tok_slot[t * 2 + k2] = slot;
    }
}

// ---------------------------------------------------------------- maxes / scales
__global__ void max_abs_kernel(const float* __restrict__ src, int n4, int slot) {
    float m = 0.f;
    for (size_t i = (size_t)blockIdx.x * blockDim.x + threadIdx.x; i < (size_t)n4;
         i += (size_t)gridDim.x * blockDim.x) {
        float4 v = ((const float4*)src)[i];
        m = fmaxf(m, fmaxf(fmaxf(fabsf(v.x), fabsf(v.y)),
                           fmaxf(fabsf(v.z), fabsf(v.w))));
    }
#pragma unroll
    for (int o = 16; o; o >>= 1) m = fmaxf(m, __shfl_xor_sync(~0u, m, o));
    __shared__ float sm[8];
    if ((threadIdx.x & 31) == 0) sm[threadIdx.x >> 5] = m;
    __syncthreads();
    if (threadIdx.x < 8) {
        m = sm[threadIdx.x];
#pragma unroll
        for (int o = 4; o; o >>= 1) m = fmaxf(m, __shfl_xor_sync(0xFFu, m, o));
        if (threadIdx.x == 0) atomicMax(&g_max[slot], __float_as_int(m));
    }
}

__global__ void scale1_kernel() {
    if (threadIdx.x != 0) return;
    float mx = fmaxf(__int_as_float(g_max[0]), 1e-20f);
    float m1 = fmaxf(__int_as_float(g_max[1]), 1e-20f);
    float m2 = fmaxf(__int_as_float(g_max[2]), 1e-20f);
    float mp = fmaxf(__int_as_float(g_max[3]), 1e-20f);
    g_scl[0] = 32600.f / mx;
    g_scl[1] = 32600.f / m1;
    g_scl[2] = 32600.f / m2;
    g_scl[3] = 32600.f / mp;
    g_scl[5] = (mx / 32600.f) * (m1 / 32600.f);
    g_scl[6] = (mx / 32600.f) * (m2 / 32600.f);
}

__global__ void scale2_kernel() {
    if (threadIdx.x != 0) return;
    float ma = fmaxf(__int_as_float(g_max[4]), 1e-20f);
    float mp = fmaxf(__int_as_float(g_max[3]), 1e-20f);
    g_scl[4] = 32600.f / ma;
    g_scl[7] = (ma / 32600.f) * (mp / 32600.f);
}

// ---------------------------------------------------------------- quantize
__device__ __forceinline__ void quant4(float4 v, float inv,
                                       uint32_t* ph, uint32_t* pl) {
    float vv[4] = { v.x, v.y, v.z, v.w };
    uint32_t h = 0, l = 0;
#pragma unroll
    for (int j = 0; j < 4; j++) {
        int q = __float2int_rn(vv[j] * inv);
        q = max(-32640, min(32639, q));
        int hi = (q + 128) >> 8;
        int lo = q - (hi << 8);
        h |= ((uint32_t)(uint8_t)hi) << (8 * j);
        l |= ((uint32_t)(uint8_t)lo) << (8 * j);
    }
    *ph = h; *pl = l;
}

__global__ void quantize_x_kernel(const float* __restrict__ x) {
    if (!flag_on()) return;
    float inv = g_scl[0];
    size_t i = (size_t)blockIdx.x * 256 + threadIdx.x;
    quant4(((const float4*)x)[i], inv, &g_xqh[i], &g_xql[i]);
}

// W [E][R][C] -> packed [e][c][r4]
__global__ void tq_w_kernel(const float* __restrict__ W,
                            uint32_t* __restrict__ Oh, uint32_t* __restrict__ Ol,
                            int R, int C, int stag)
{
    if (!flag_on()) return;
    __shared__ float tile[32][33];
    int e = blockIdx.z;
    int c0 = blockIdx.x * 32, r0 = blockIdx.y * 32;
    int tx = threadIdx.x & 31, ty = threadIdx.x >> 5;
    const float* src = W + (size_t)e * R * C;
#pragma unroll
    for (int i = 0; i < 32; i += 8)
        tile[ty + i][tx] = src[(size_t)(r0 + ty + i) * C + c0 + tx];
    __syncthreads();
    float inv = g_scl[stag];
    int cl = threadIdx.x >> 3, j = threadIdx.x & 7;
    float4 v = make_float4(tile[j * 4 + 0][cl], tile[j * 4 + 1][cl],
                           tile[j * 4 + 2][cl], tile[j * 4 + 3][cl]);
    uint32_t h, l;
    quant4(v, inv, &h, &l);
    size_t oidx = ((size_t)e * C + c0 + cl) * (size_t)(R / 4) + (r0 >> 2) + j;
    Oh[oidx] = h; Ol[oidx] = l;
}

// ---------------------------------------------------------------- int GEMM
// C[off[e]+m, n] = (65536*S_hh + 256*S_mid) * scale + bias
__global__ __launch_bounds__(256) void igemm_kernel(
    const uint32_t* __restrict__ Ah, const uint32_t* __restrict__ Al,
    const uint32_t* __restrict__ Bh, const uint32_t* __restrict__ Bl,
    const float* __restrict__ bias, float* __restrict__ C,
    int K4, int Ndim, int gather, int stag)
{
    if (!flag_on()) return;
    __shared__ uint32_t sAh[128][8], sAl[128][8];
    __shared__ uint32_t sBh[8][64], sBl[8][64];

    int e = blockIdx.z;
    int cnt = g_cnt[e];
    int mbase = blockIdx.y * 128;
    if (mbase >= cnt) return;
    int off = g_off[e];
    int mrem = min(128, cnt - mbase);
    int n0g = blockIdx.x * 64;

    int tid = threadIdx.x;
    int m0 = (tid >> 4) * 8;
    int n0w = (tid & 15) * 4;

    // A loader: each thread one 16B chunk (4 u32) per buffer
    int lr = tid >> 1, lj = (tid & 1) * 4;
    int lrr = min(lr, mrem - 1);
    int rowid = gather ? g_slot_token[off + mbase + lrr] : (off + mbase + lrr);
    const uint32_t* aH = Ah + (size_t)rowid * K4 + lj;
    const uint32_t* aL = Al + (size_t)rowid * K4 + lj;

    // B loader: each thread one uint2 per buffer
    int bn = tid & 63, bj = (tid >> 6) * 2;
    const uint32_t* bH = Bh + ((size_t)e * Ndim + n0g + bn) * K4 + bj;
    const uint32_t* bL = Bl + ((size_t)e * Ndim + n0g + bn) * K4 + bj;

    int hh[8][4], mid[8][4];
#pragma unroll
    for (int m = 0; m < 8; m++)
#pragma unroll
        for (int n = 0; n < 4; n++) { hh[m][n] = 0; mid[m][n] = 0; }

    const int NC = K4 / 8;
    uint4 pAh = *(const uint4*)aH;
    uint4 pAl = *(const uint4*)aL;
    uint2 pBh = *(const uint2*)bH;
    uint2 pBl = *(const uint2*)bL;

    for (int c = 0; c < NC; c++) {
        *(uint4*)&sAh[lr][lj] = pAh;
        *(uint4*)&sAl[lr][lj] = pAl;
        sBh[bj][bn] = pBh.x; sBh[bj + 1][bn] = pBh.y;
        sBl[bj][bn] = pBl.x; sBl[bj + 1][bn] = pBl.y;
        __syncthreads();
        if (c + 1 < NC) {
            int k0 = (c + 1) * 8;
            pAh = *(const uint4*)(aH + k0);
            pAl = *(const uint4*)(aL + k0);
            pBh = *(const uint2*)(bH + k0);
            pBl = *(const uint2*)(bL + k0);
        }
#pragma unroll
        for (int j = 0; j < 8; j += 2) {
            uint2 fah[8], fal[8];
#pragma unroll
            for (int m = 0; m < 8; m++) {
                fah[m] = *(const uint2*)&sAh[m0 + m][j];
                fal[m] = *(const uint2*)&sAl[m0 + m][j];
            }
            uint4 q;
            uint32_t bh0[4], bh1[4], bl0[4], bl1[4];
            q = *(const uint4*)&sBh[j][n0w];
            bh0[0] = q.x; bh0[1] = q.y; bh0[2] = q.z; bh0[3] = q.w;
            q = *(const uint4*)&sBh[j + 1][n0w];
            bh1[0] = q.x; bh1[1] = q.y; bh1[2] = q.z; bh1[3] = q.w;
            q = *(const uint4*)&sBl[j][n0w];
            bl0[0] = q.x; bl0[1] = q.y; bl0[2] = q.z; bl0[3] = q.w;
            q = *(const uint4*)&sBl[j + 1][n0w];
            bl1[0] = q.x; bl1[1] = q.y; bl1[2] = q.z; bl1[3] = q.w;
#pragma unroll
            for (int m = 0; m < 8; m++)
#pragma unroll
                for (int n = 0; n < 4; n++) {
                    hh[m][n]  = __dp4a((int)fah[m].x, (int)bh0[n], hh[m][n]);
                    hh[m][n]  = __dp4a((int)fah[m].y, (int)bh1[n], hh[m][n]);
                    mid[m][n] = __dp4a((int)fah[m].x, (int)bl0[n], mid[m][n]);
                    mid[m][n] = __dp4a((int)fah[m].y, (int)bl1[n], mid[m][n]);
                    mid[m][n] = __dp4a((int)fal[m].x, (int)bh0[n], mid[m][n]);
                    mid[m][n] = __dp4a((int)fal[m].y, (int)bh1[n], mid[m][n]);
                }
        }
        __syncthreads();
    }

    float s = g_scl[stag];
#pragma unroll
    for (int m = 0; m < 8; m++) {
        int gm = m0 + m;
        if (gm < mrem) {
            size_t row = (size_t)(off + mbase + gm);
            float4 v;
            v.x = ((float)hh[m][0] * 65536.f + (float)mid[m][0] * 256.f) * s
                  + bias[e * Ndim + n0g + n0w + 0];
            v.y = ((float)hh[m][1] * 65536.f + (float)mid[m][1] * 256.f) * s
                  + bias[e * Ndim + n0g + n0w + 1];
            v.z = ((float)hh[m][2] * 65536.f + (float)mid[m][2] * 256.f) * s
                  + bias[e * Ndim + n0g + n0w + 2];
            v.w = ((float)hh[m][3] * 65536.f + (float)mid[m][3] * 256.f) * s
                  + bias[e * Ndim + n0g + n0w + 3];
            *(float4*)(C + row * Ndim + n0g + n0w) = v;
        }
    }
}

// ---------------------------------------------------------------- act (int path)
__global__ void act_int_kernel() {
    if (!flag_on()) return;
    size_t i = (size_t)blockIdx.x * 256 + threadIdx.x;
    float4 h4 = ((float4*)g_h)[i];
    const float4 g4 = ((const float4*)g_g)[i];
    h4.x = h4.x * (g4.x / (1.f + expf(-g4.x)));
    h4.y = h4.y * (g4.y / (1.f + expf(-g4.y)));
    h4.z = h4.z * (g4.z / (1.f + expf(-g4.z)));
    h4.w = h4.w * (g4.w / (1.f + expf(-g4.w)));
    ((float4*)g_h)[i] = h4;
    float m = fmaxf(fmaxf(fabsf(h4.x), fabsf(h4.y)), fmaxf(fabsf(h4.z), fabsf(h4.w)));
#pragma unroll
    for (int o = 16; o; o >>= 1) m = fmaxf(m, __shfl_xor_sync(~0u, m, o));
    if ((threadIdx.x & 31) == 0) atomicMax(&g_max[4], __float_as_int(m));
}

__global__ void quantize_act_kernel() {
    if (!flag_on()) return;
    float inv = g_scl[4];
    size_t i = (size_t)blockIdx.x * 256 + threadIdx.x;
    quant4(((const float4*)g_h)[i], inv, &g_aqh[i], &g_aql[i]);
}

// ---------------------------------------------------------------- verifies
__global__ void verify12_kernel(const float* __restrict__ x,
                                const float* __restrict__ w1, const float* __restrict__ b1,
                                const float* __restrict__ w2, const float* __restrict__ b2)
{
    if (!flag_on()) return;
    int b = blockIdx.x, tid = threadIdx.x;
    int s = (b * 709 + 13) % NSLOT;
    int col = (b * 397 + 7) % HDIM;
    int e = 0;
#pragma unroll
    for (int i = 1; i < NE; i++) if (s >= g_off[i]) e = i;
    int tok = g_slot_token[s];
    float ph = 0.f, pg = 0.f;
    for (int d = tid; d < DDIM; d += 256) {
        float xv = x[(size_t)tok * DDIM + d];
        ph += xv * w1[((size_t)e * DDIM + d) * HDIM + col];
        pg += xv * w2[((size_t)e * DDIM + d) * HDIM + col];
    }
    __shared__ float sh[256], sg[256];
    sh[tid] = ph; sg[tid] = pg;
    __syncthreads();
    for (int st = 128; st > 0; st >>= 1) {
        if (tid < st) { sh[tid] += sh[tid + st]; sg[tid] += sg[tid + st]; }
        __syncthreads();
    }
    if (tid == 0) {
        float h = sh[0] + b1[e * HDIM + col];
        float g = sg[0] + b2[e * HDIM + col];
        float ref = h * (g / (1.f + expf(-g)));
        float got = g_h[(size_t)s * HDIM + col];   // act fp32 from int path
        if (fabsf(got - ref) > fmaxf(fabsf(ref) * 0.05f, 0.05f)) atomicExch(&g_ok, 0);
    }
}

__global__ void verify3_kernel(const float* __restrict__ wp, const float* __restrict__ bp)
{
    if (!flag_on()) return;
    int b = blockIdx.x, tid = threadIdx.x;
    int s = (b * 547 + 29) % NSLOT;
    int c = (b * 131 + 3) % DDIM;
    int e = 0;
#pragma unroll
    for (int i = 1; i < NE; i++) if (s >= g_off[i]) e = i;
    float p = 0.f;
    for (int hh = tid; hh < HDIM; hh += 256) {
        float av = g_h[(size_t)s * HDIM + hh];     // act fp32
        p += av * wp[((size_t)e * HDIM + hh) * DDIM + c];
    }
    __shared__ float sh[256];
    sh[tid] = p;
    __syncthreads();
    for (int st = 128; st > 0; st >>= 1) {
        if (tid < st) sh[tid] += sh[tid + st];
        __syncthreads();
    }
    if (tid == 0) {
        float ref = sh[0] + bp[e * DDIM + c];
        float got = g_y[(size_t)s * DDIM + c];
        if (fabsf(got - ref) > fmaxf(fabsf(ref) * 0.05f, 0.05f)) atomicExch(&g_ok, 0);
    }
}

// ---------------------------------------------------------------- scalar fallback
__global__ __launch_bounds__(256, 2)
void sgemm_scalar(const float* __restrict__ X,
                  const float* __restrict__ W,
                  const float* __restrict__ bias,
                  int Kdim, int Ndim, int mode)
{
    if (flag_on()) return;
    int e = blockIdx.z;
    int cnt = g_cnt[e];
    int mbase = blockIdx.y * BM;
    if (mbase >= cnt) return;
    int off = g_off[e];
    int mrem = cnt - mbase;
    int n0 = blockIdx.x * BN;

    float* C = (mode == 0) ? g_h : (mode == 1) ? g_g : g_y;
    const float* A = (mode == 2) ? g_h : X;

    const float* arp[2];
#pragma unroll
    for (int i = 0; i < 2; i++) {
        int idx = threadIdx.x + i * 256;
        int ar = idx >> 2;
        int r = (ar < mrem) ? ar : 0;
        int slot = off + mbase + r;
        if (mode == 2) arp[i] = A + (size_t)slot * Kdim;
        else           arp[i] = A + (size_t)g_slot_token[slot] * Kdim;
    }
    const float* Wp = W + (size_t)e * Kdim * Ndim + n0;

    __shared__ float As[BK][BM];
    __shared__ float Bs[BK][BN];

    float accv[8][8];
#pragma unroll
    for (int mi = 0; mi < 8; mi++)
#pragma unroll
        for (int ni = 0; ni < 8; ni++) accv[mi][ni] = 0.f;

    int tx = threadIdx.x & 15;
    int ty = threadIdx.x >> 4;
    int mt = ty * 8;
    int nt = tx * 8;

    for (int k0 = 0; k0 < Kdim; k0 += BK) {
#pragma unroll
        for (int i = 0; i < 2; i++) {
            int idx = threadIdx.x + i * 256;
            int ar = idx >> 2, a4 = idx & 3;
            float4 v = *(const float4*)(arp[i] + k0 + a4 * 4);
            As[a4 * 4 + 0][ar] = v.x;
            As[a4 * 4 + 1][ar] = v.y;
            As[a4 * 4 + 2][ar] = v.z;
            As[a4 * 4 + 3][ar] = v.w;
        }
#pragma unroll
        for (int i = 0; i < 2; i++) {
            int idx = threadIdx.x + i * 256;
            int br = idx >> 5, b4 = idx & 31;
            *(float4*)&Bs[br][b4 * 4] =
                *(const float4*)(Wp + (size_t)(k0 + br) * Ndim + b4 * 4);
        }
        __syncthreads();
#pragma unroll
        for (int k = 0; k < BK; k++) {
            float a[8], bb[8];
            *(float4*)&a[0] = *(const float4*)&As[k][mt];
            *(float4*)&a[4] = *(const float4*)&As[k][mt + 4];
            *(float4*)&bb[0] = *(const float4*)&Bs[k][nt];
            *(float4*)&bb[4] = *(const float4*)&Bs[k][nt + 4];
#pragma unroll
            for (int mi = 0; mi < 8; mi++)
#pragma unroll
                for (int ni = 0; ni < 8; ni++)
                    accv[mi][ni] += a[mi] * bb[ni];
        }
        __syncthreads();
    }

    float bl[8];
    *(float4*)&bl[0] = *(const float4*)(bias + (size_t)e * Ndim + n0 + nt);
    *(float4*)&bl[4] = *(const float4*)(bias + (size_t)e * Ndim + n0 + nt + 4);

#pragma unroll
    for (int mi = 0; mi < 8; mi++) {
        int gm = mt + mi;
        if (gm < mrem) {
            size_t row = (size_t)(off + mbase + gm);
            float* cp = C + row * Ndim + n0 + nt;
            float4 v0 = make_float4(accv[mi][0] + bl[0], accv[mi][1] + bl[1],
                                    accv[mi][2] + bl[2], accv[mi][3] + bl[3]);
            float4 v1 = make_float4(accv[mi][4] + bl[4], accv[mi][5] + bl[5],
                                    accv[mi][6] + bl[6], accv[mi][7] + bl[7]);
            *(float4*)cp = v0;
            *(float4*)(cp + 4) = v1;
        }
    }
}

__global__ void act_fb_kernel() {
    if (flag_on()) return;
    size_t i = (size_t)blockIdx.x * 256 + threadIdx.x;
    float4* hp = (float4*)g_h;
    const float4* gp = (const float4*)g_g;
    float4 g4 = gp[i];
    float4 h4 = hp[i];
    h4.x = h4.x * (g4.x / (1.f + expf(-g4.x)));
    h4.y = h4.y * (g4.y / (1.f + expf(-g4.y)));
    h4.z = h4.z * (g4.z / (1.f + expf(-g4.z)));
    h4.w = h4.w * (g4.w / (1.f + expf(-g4.w)));
    hp[i] = h4;
}

// ---------------------------------------------------------------- combine
__global__ void combine_kernel(float* __restrict__ out) {
    int f = blockIdx.x * blockDim.x + threadIdx.x;
    int t = f / (DDIM / 4);
    int j = f % (DDIM / 4);
    int s0 = g_tok_slot[t * 2 + 0];
    int s1 = g_tok_slot[t * 2 + 1];
    float g0 = g_tok_gate[t * 2 + 0];
    float g1 = g_tok_gate[t * 2 + 1];
    const float4* y = (const float4*)g_y;
    float4 a = y[(size_t)s0 * (DDIM / 4) + j];
    float4 b = y[(size_t)s1 * (DDIM / 4) + j];
    float4 o;
    o.x = g0 * a.x + g1 * b.x;
    o.y = g0 * a.y + g1 * b.y;
    o.z = g0 * a.z + g1 * b.z;
    o.w = g0 * a.w + g1 * b.w;
    ((float4*)out)[f] = o;
}

// ---------------------------------------------------------------- launch
extern "C" void kernel_launch(void* const* d_in, const int* in_sizes, int n_in,
                              void* d_out, int out_size)
{
    const float* x     = (const float*)d_in[0];
    const float* noise = (const float*)d_in[1];
    const float* gw    = (const float*)d_in[2];
    const float* nw    = (const float*)d_in[3];
    const float* w1    = (const float*)d_in[4];
    const float* b1    = (const float*)d_in[5];
    const float* w2    = (const float*)d_in[6];
    const float* b2    = (const float*)d_in[7];
    const float* wp    = (const float*)d_in[8];
    const float* bp    = (const float*)d_in[9];

    float* out = (float*)d_out;
    float* out_ids = nullptr;
    float* out_lb  = nullptr;
    if (out_size >= T_TOK * DDIM + NSLOT)     out_ids = out + (size_t)T_TOK * DDIM;
    if (out_size >= T_TOK * DDIM + NSLOT + 1) out_lb  = out + (size_t)T_TOK * DDIM + NSLOT;

    zero_stats<<<1, 32>>>();
    gate_kernel<<<T_TOK, 128>>>(x, noise, gw, nw, out_ids);
    finalize_kernel<<<1, 1>>>(out_lb);
    scatter_kernel<<<(T_TOK + 255) / 256, 256>>>();

    // ---- maxes + scales ----
    max_abs_kernel<<<256, 256>>>(x, T_TOK * DDIM / 4, 0);
    max_abs_kernel<<<2048, 256>>>(w1, (int)((size_t)NE * DDIM * HDIM / 4), 1);
    max_abs_kernel<<<2048, 256>>>(w2, (int)((size_t)NE * DDIM * HDIM / 4), 2);
    max_abs_kernel<<<2048, 256>>>(wp, (int)((size_t)NE * HDIM * DDIM / 4), 3);
    scale1_kernel<<<1, 1>>>();

    // ---- quantize + pack ----
    quantize_x_kernel<<<T_TOK * K4X / 256, 256>>>(x);
    tq_w_kernel<<<dim3(HDIM / 32, DDIM / 32, NE), 256>>>(w1, g_w1qh, g_w1ql, DDIM, HDIM, 1);
    tq_w_kernel<<<dim3(HDIM / 32, DDIM / 32, NE), 256>>>(w2, g_w2qh, g_w2ql, DDIM, HDIM, 2);
    tq_w_kernel<<<dim3(DDIM / 32, HDIM / 32, NE), 256>>>(wp, g_wpqh, g_wpql, HDIM, DDIM, 3);

    // ---- int GEMM path ----
    igemm_kernel<<<dim3(HDIM / 64, NSLOT / 128, NE), 256>>>(
        g_xqh, g_xql, g_w1qh, g_w1ql, b1, g_h, K4X, HDIM, 1, 5);
    igemm_kernel<<<dim3(HDIM / 64, NSLOT / 128, NE), 256>>>(
        g_xqh, g_xql, g_w2qh, g_w2ql, b2, g_g, K4X, HDIM, 1, 6);
    act_int_kernel<<<(size_t)NSLOT * HDIM / 4 / 256, 256>>>();
    scale2_kernel<<<1, 1>>>();
    quantize_act_kernel<<<(size_t)NSLOT * K4H / 256, 256>>>();
    verify12_kernel<<<64, 256>>>(x, w1, b1, w2, b2);
    igemm_kernel<<<dim3(DDIM / 64, NSLOT / 128, NE), 256>>>(
        g_aqh, g_aql, g_wpqh, g_wpql, bp, g_y, K4H, DDIM, 0, 7);
    verify3_kernel<<<64, 256>>>(wp, bp);

    // ---- scalar fallback (runs only if a check failed) ----
    dim3 gs1(HDIM / BN, T_TOK / BM, NE);
    sgemm_scalar<<<gs1, 256>>>(x, w1, b1, DDIM, HDIM, 0);
    sgemm_scalar<<<gs1, 256>>>(x, w2, b2, DDIM, HDIM, 1);
    act_fb_kernel<<<(size_t)NSLOT * HDIM / 4 / 256, 256>>>();
    dim3 gs2(DDIM / BN, T_TOK / BM, NE);
    sgemm_scalar<<<gs2, 256>>>(nullptr, wp, bp, HDIM, DDIM, 2);

    combine_kernel<<<T_TOK * DDIM / 4 / 256, 256>>>(out);
}

// round 9
// speedup vs baseline: 5.7923x; 5.7923x over previous
#include <cuda_runtime.h>
#include <cstdint>
#include <math.h>

#define T_TOK 2048
#define NE 8
#define DDIM 768
#define HDIM 3072
#define NSLOT (T_TOK * 2)

#define BM 128
#define BN 128
#define BK 16

typedef unsigned long long u64;

// ---------------- scratch (device globals; no allocations allowed) ----------
__device__ float g_h[(size_t)NSLOT * HDIM];   // h, then act in place
__device__ float g_g[(size_t)NSLOT * HDIM];   // g
__device__ float g_y[(size_t)NSLOT * DDIM];   // per-slot expert output
__device__ int   g_cnt[NE];
__device__ int   g_cnt2[NE];
__device__ int   g_off[NE];
__device__ float g_probs[NE];
__device__ int   g_slot_token[NSLOT];
__device__ int   g_tok_slot[NSLOT];
__device__ float g_tok_gate[NSLOT];
__device__ int   g_tok_exp[NSLOT];

// ---------------- kernels ---------------------------------------------------
__global__ void zero_stats()
{
    int i = threadIdx.x;
    if (i < NE) { g_cnt[i] = 0; g_probs[i] = 0.f; }
}

__global__ void gate_kernel(const float* __restrict__ x,
                            const float* __restrict__ noise,
                            const float* __restrict__ gw,
                            const float* __restrict__ nw,
                            float* __restrict__ out_ids)
{
    int t = blockIdx.x;
    int tid = threadIdx.x;              // 128 threads
    const float* xr = x + (size_t)t * DDIM;

    float acc[NE];
#pragma unroll
    for (int e = 0; e < NE; e++) acc[e] = 0.f;

    for (int d = tid; d < DDIM; d += 128) {
        float xv = xr[d];
        const float* w = gw + d * NE;
#pragma unroll
        for (int e = 0; e < NE; e++) acc[e] += xv * w[e];
    }

    __shared__ float sm[NE][128];
#pragma unroll
    for (int e = 0; e < NE; e++) sm[e][tid] = acc[e];
    __syncthreads();
    for (int s = 64; s > 0; s >>= 1) {
        if (tid < s) {
#pragma unroll
            for (int e = 0; e < NE; e++) sm[e][tid] += sm[e][tid + s];
        }
        __syncthreads();
    }

    if (tid == 0) {
        float lg[NE], ns[NE];
#pragma unroll
        for (int e = 0; e < NE; e++) {
            lg[e] = sm[e][0];
            ns[e] = lg[e] + noise[t * NE + e] * nw[e];
        }
        // top-2 (strict >, ties keep lower index, matching jax top_k)
        int i0 = 0;
#pragma unroll
        for (int e = 1; e < NE; e++) if (ns[e] > ns[i0]) i0 = e;
        int i1 = (i0 == 0) ? 1 : 0;
#pragma unroll
        for (int e = 0; e < NE; e++) if (e != i0 && ns[e] > ns[i1]) i1 = e;

        float q  = expf(ns[i1] - ns[i0]);   // <= 1
        float p1 = q / (1.f + q);
        float p0 = 1.f - p1;

        g_tok_exp[t * 2 + 0] = i0;  g_tok_exp[t * 2 + 1] = i1;
        g_tok_gate[t * 2 + 0] = p0; g_tok_gate[t * 2 + 1] = p1;
        if (out_ids) {
            out_ids[t * 2 + 0] = (float)i0;
            out_ids[t * 2 + 1] = (float)i1;
        }
        atomicAdd(&g_cnt[i0], 1);
        atomicAdd(&g_cnt[i1], 1);

        // clean-logit softmax for the load-balance loss
        float m = lg[0];
#pragma unroll
        for (int e = 1; e < NE; e++) m = fmaxf(m, lg[e]);
        float ex[NE], sum = 0.f;
#pragma unroll
        for (int e = 0; e < NE; e++) { ex[e] = expf(lg[e] - m); sum += ex[e]; }
        float inv = 1.f / sum;
#pragma unroll
        for (int e = 0; e < NE; e++) atomicAdd(&g_probs[e], ex[e] * inv);
    }
}

__global__ void finalize_kernel(float* __restrict__ out_lb)
{
    if (threadIdx.x == 0 && blockIdx.x == 0) {
        int off = 0;
        for (int e = 0; e < NE; e++) {
            g_off[e] = off;
            off += g_cnt[e];
            g_cnt2[e] = 0;
        }
        float accv = 0.f;
        for (int e = 0; e < NE; e++) {
            float d = g_probs[e] / (float)T_TOK - 1.0f / (float)NE;
            accv += d * d;
        }
        if (out_lb) out_lb[0] = accv / (float)NE * 0.01f;
    }
}

__global__ void scatter_kernel()
{
    int t = blockIdx.x * blockDim.x + threadIdx.x;
    if (t >= T_TOK) return;
#pragma unroll
    for (int k2 = 0; k2 < 2; k2++) {
        int e = g_tok_exp[t * 2 + k2];
        int pos = atomicAdd(&g_cnt2[e], 1);
        int slot = g_off[e] + pos;
        g_slot_token[slot] = t;
        g_tok_slot[t * 2 + k2] = slot;
    }
}

// Grouped SGEMM with packed f32x2 FMA (accumulators paired along M).
// C[off[e]+m, n] = sum_k A[m,k] * W[e,k,n] + bias[e,n]
// mode 0: A = x gathered rows -> C = g_h
// mode 1: A = x gathered rows -> C = g_g
// mode 2: A = g_h (dense per-expert slot rows) -> C = g_y
// A pairs along m come free from As[k][m] (aligned LDS.64, broadcast across
// the 16 n-threads). B values are duplicated into (b,b) via register packs
// on the ALU pipe — zero extra shared-memory traffic vs the fp32 kernel.
__global__ __launch_bounds__(256, 2)
void sgemm_kernel(const float* __restrict__ X,
                  const float* __restrict__ W,
                  const float* __restrict__ bias,
                  int Kdim, int Ndim, int mode)
{
    int e = blockIdx.z;
    int cnt = g_cnt[e];
    int mbase = blockIdx.y * BM;
    if (mbase >= cnt) return;
    int off = g_off[e];
    int mrem = cnt - mbase;                 // 1..128 valid rows in this tile
    int n0 = blockIdx.x * BN;

    float* C = (mode == 0) ? g_h : (mode == 1) ? g_g : g_y;
    const float* A = (mode == 2) ? g_h : X;

    // precompute the 2 gathered row pointers this thread loads from
    const float* arp[2];
#pragma unroll
    for (int i = 0; i < 2; i++) {
        int idx = threadIdx.x + i * 256;
        int ar = idx >> 2;
        int r = (ar < mrem) ? ar : 0;       // clamp invalid rows to a valid one
        int slot = off + mbase + r;
        if (mode == 2) arp[i] = A + (size_t)slot * Kdim;
        else           arp[i] = A + (size_t)g_slot_token[slot] * Kdim;
    }
    const float* Wp = W + (size_t)e * Kdim * Ndim + n0;

    __shared__ __align__(16) float As[BK][BM];   // 8 KB
    __shared__ __align__(16) float Bs[BK][BN];   // 8 KB

    u64 acc[4][8];                   // [m-pair][n], 64 fp32 accumulators
#pragma unroll
    for (int mp = 0; mp < 4; mp++)
#pragma unroll
        for (int n = 0; n < 8; n++) acc[mp][n] = 0ULL;

    int tx = threadIdx.x & 15;
    int ty = threadIdx.x >> 4;
    int mt = ty * 8;
    int nt = tx * 8;

    for (int k0 = 0; k0 < Kdim; k0 += BK) {
#pragma unroll
        for (int i = 0; i < 2; i++) {
            int idx = threadIdx.x + i * 256;
            int ar = idx >> 2, a4 = idx & 3;
            float4 v = *(const float4*)(arp[i] + k0 + a4 * 4);
            As[a4 * 4 + 0][ar] = v.x;
            As[a4 * 4 + 1][ar] = v.y;
            As[a4 * 4 + 2][ar] = v.z;
            As[a4 * 4 + 3][ar] = v.w;
        }
#pragma unroll
        for (int i = 0; i < 2; i++) {
            int idx = threadIdx.x + i * 256;
            int br = idx >> 5, b4 = idx & 31;
            *(float4*)&Bs[br][b4 * 4] =
                *(const float4*)(Wp + (size_t)(k0 + br) * Ndim + b4 * 4);
        }
        __syncthreads();
#pragma unroll
        for (int k = 0; k < BK; k++) {
            // 4 aligned m-pairs straight from shared memory
            u64 a2[4];
            const u64* arow = (const u64*)&As[k][mt];
            a2[0] = arow[0]; a2[1] = arow[1]; a2[2] = arow[2]; a2[3] = arow[3];
            // 8 b values, duplicated into (b,b) via register packs (ALU pipe)
            float bb[8];
            *(float4*)&bb[0] = *(const float4*)&Bs[k][nt];
            *(float4*)&bb[4] = *(const float4*)&Bs[k][nt + 4];
            u64 bd[8];
#pragma unroll
            for (int n = 0; n < 8; n++) {
                uint32_t r = __float_as_uint(bb[n]);
                asm("mov.b64 %0, {%1, %1};" : "=l"(bd[n]) : "r"(r));
            }
#pragma unroll
            for (int mp = 0; mp < 4; mp++)
#pragma unroll
                for (int n = 0; n < 8; n++)
                    asm("fma.rn.f32x2 %0, %1, %2, %0;"
                        : "+l"(acc[mp][n]) : "l"(a2[mp]), "l"(bd[n]));
        }
        __syncthreads();
    }

    // unpack accumulators: acc[mp][n] = (m=mt+2mp, m=mt+2mp+1) for column n
    float cv[8][8];
#pragma unroll
    for (int mp = 0; mp < 4; mp++)
#pragma unroll
        for (int n = 0; n < 8; n++) {
            float lo, hi;
            asm("mov.b64 {%0, %1}, %2;" : "=f"(lo), "=f"(hi) : "l"(acc[mp][n]));
            cv[mp * 2 + 0][n] = lo;
            cv[mp * 2 + 1][n] = hi;
        }

    float bl[8];
    *(float4*)&bl[0] = *(const float4*)(bias + (size_t)e * Ndim + n0 + nt);
    *(float4*)&bl[4] = *(const float4*)(bias + (size_t)e * Ndim + n0 + nt + 4);

#pragma unroll
    for (int mi = 0; mi < 8; mi++) {
        int gm = mt + mi;
        if (gm < mrem) {
            size_t row = (size_t)(off + mbase + gm);
            float* cp = C + row * Ndim + n0 + nt;
            float4 v0 = make_float4(cv[mi][0] + bl[0], cv[mi][1] + bl[1],
                                    cv[mi][2] + bl[2], cv[mi][3] + bl[3]);
            float4 v1 = make_float4(cv[mi][4] + bl[4], cv[mi][5] + bl[5],
                                    cv[mi][6] + bl[6], cv[mi][7] + bl[7]);
            *(float4*)cp = v0;
            *(float4*)(cp + 4) = v1;
        }
    }
}

__global__ void act_kernel()
{
    size_t i = (size_t)blockIdx.x * blockDim.x + threadIdx.x;  // over float4
    float4* hp = (float4*)g_h;
    const float4* gp = (const float4*)g_g;
    float4 g4 = gp[i];
    float4 h4 = hp[i];
    h4.x = h4.x * (g4.x / (1.f + expf(-g4.x)));
    h4.y = h4.y * (g4.y / (1.f + expf(-g4.y)));
    h4.z = h4.z * (g4.z / (1.f + expf(-g4.z)));
    h4.w = h4.w * (g4.w / (1.f + expf(-g4.w)));
    hp[i] = h4;
}

__global__ void combine_kernel(float* __restrict__ out)
{
    int f = blockIdx.x * blockDim.x + threadIdx.x;  // over float4 of out
    int t = f / (DDIM / 4);
    int j = f % (DDIM / 4);
    int s0 = g_tok_slot[t * 2 + 0];
    int s1 = g_tok_slot[t * 2 + 1];
    float g0 = g_tok_gate[t * 2 + 0];
    float g1 = g_tok_gate[t * 2 + 1];
    const float4* y = (const float4*)g_y;
    float4 a = y[(size_t)s0 * (DDIM / 4) + j];
    float4 b = y[(size_t)s1 * (DDIM / 4) + j];
    float4 o;
    o.x = g0 * a.x + g1 * b.x;
    o.y = g0 * a.y + g1 * b.y;
    o.z = g0 * a.z + g1 * b.z;
    o.w = g0 * a.w + g1 * b.w;
    ((float4*)out)[f] = o;
}

// ---------------- launch -----------------------------------------------------
extern "C" void kernel_launch(void* const* d_in, const int* in_sizes, int n_in,
                              void* d_out, int out_size)
{
    const float* x     = (const float*)d_in[0];
    const float* noise = (const float*)d_in[1];
    const float* gw    = (const float*)d_in[2];
    const float* nw    = (const float*)d_in[3];
    const float* w1    = (const float*)d_in[4];
    const float* b1    = (const float*)d_in[5];
    const float* w2    = (const float*)d_in[6];
    const float* b2    = (const float*)d_in[7];
    const float* wp    = (const float*)d_in[8];
    const float* bp    = (const float*)d_in[9];

    float* out = (float*)d_out;
    float* out_ids = nullptr;
    float* out_lb  = nullptr;
    if (out_size >= T_TOK * DDIM + NSLOT)     out_ids = out + (size_t)T_TOK * DDIM;
    if (out_size >= T_TOK * DDIM + NSLOT + 1) out_lb  = out + (size_t)T_TOK * DDIM + NSLOT;

    zero_stats<<<1, 32>>>();
    gate_kernel<<<T_TOK, 128>>>(x, noise, gw, nw, out_ids);
    finalize_kernel<<<1, 1>>>(out_lb);
    scatter_kernel<<<(T_TOK + 255) / 256, 256>>>();

    dim3 g1(HDIM / BN, T_TOK / BM, NE);   // 24 x 16 x 8
    sgemm_kernel<<<g1, 256>>>(x, w1, b1, DDIM, HDIM, 0);
    sgemm_kernel<<<g1, 256>>>(x, w2, b2, DDIM, HDIM, 1);

    act_kernel<<<(size_t)NSLOT * HDIM / 4 / 256, 256>>>();

    dim3 g2(DDIM / BN, T_TOK / BM, NE);   // 6 x 16 x 8
    sgemm_kernel<<<g2, 256>>>(nullptr, wp, bp, HDIM, DDIM, 2);

    combine_kernel<<<T_TOK * DDIM / 4 / 256, 256>>>(out);
}